// round 13
// baseline (speedup 1.0000x reference)
#include <cuda_runtime.h>
#include <math.h>
#include <stdint.h>

#define NB 32
#define NG 16
#define NA 8400
#define NCLS 80
#define CAND 10
#define MAXFG (NB * NG * CAND)

// ---------------- scratch (device globals) ----------------------------------
__device__ float2        g_ci  [(size_t)NB * NG * NA];   // (cost, iou), indexed by COMPACT i
__device__ float         g_pbox[(size_t)NB * NA * 4];
__device__ int           g_ia  [(size_t)NB * NA];        // anchor -> compact index
__device__ int           g_best[(size_t)NB * NA];
__device__ int           g_cnt [(size_t)NB * NA];
__device__ int           g_gsum[(size_t)NB * NA];
__device__ int           g_ulist[(size_t)NB * NA];       // per-b packed: a | (interM<<16)
__device__ int           g_ucnt[NB];
__device__ int           g_list[MAXFG];
__device__ int           g_nfg;
__device__ int           g_done;
__device__ double        g_acc[4];   // loss_box, loss_conf, loss_cls, n_fg

static __device__ __forceinline__ void level_of(int a, int b,
                                                const float* p8, const float* p16, const float* p32,
                                                const float** P, int* HW, int* loc, float* s, int* w) {
    if (a < 6400)      { *P = p8  + (size_t)b * 85 * 6400; *HW = 6400; *loc = a;        *s = 8.f;  *w = 80; }
    else if (a < 8000) { *P = p16 + (size_t)b * 85 * 1600; *HW = 1600; *loc = a - 6400; *s = 16.f; *w = 40; }
    else               { *P = p32 + (size_t)b * 85 * 400;  *HW = 400;  *loc = a - 8000; *s = 32.f; *w = 20; }
}

static __device__ __forceinline__ void reduce1(float v, int slot) {
    int tid = threadIdx.x, lane = tid & 31, wid = tid >> 5;
    #pragma unroll
    for (int off = 16; off > 0; off >>= 1) v += __shfl_down_sync(0xffffffffu, v, off);
    __shared__ float sw[8];
    if (lane == 0) sw[wid] = v;
    __syncthreads();
    if (tid == 0) {
        float a0 = 0.f;
        #pragma unroll
        for (int i = 0; i < 8; i++) a0 += sw[i];
        atomicAdd(&g_acc[slot], (double)a0);
    }
}

static __device__ __forceinline__ void reduce4(float v0, float v1, float v2, float v3) {
    int tid = threadIdx.x, lane = tid & 31, wid = tid >> 5;
    #pragma unroll
    for (int off = 16; off > 0; off >>= 1) {
        v0 += __shfl_down_sync(0xffffffffu, v0, off);
        v1 += __shfl_down_sync(0xffffffffu, v1, off);
        v2 += __shfl_down_sync(0xffffffffu, v2, off);
        v3 += __shfl_down_sync(0xffffffffu, v3, off);
    }
    __shared__ float sw[8][4];
    if (lane == 0) { sw[wid][0] = v0; sw[wid][1] = v1; sw[wid][2] = v2; sw[wid][3] = v3; }
    __syncthreads();
    if (tid == 0) {
        float a0 = 0, a1 = 0, a2 = 0, a3 = 0;
        #pragma unroll
        for (int i = 0; i < 8; i++) { a0 += sw[i][0]; a1 += sw[i][1]; a2 += sw[i][2]; a3 += sw[i][3]; }
        if (a0 != 0.f) atomicAdd(&g_acc[0], (double)a0);
        if (a1 != 0.f) atomicAdd(&g_acc[1], (double)a1);
        if (a2 != 0.f) atomicAdd(&g_acc[2], (double)a2);
        if (a3 != 0.f) atomicAdd(&g_acc[3], (double)a3);
    }
}

// ---------------- init --------------------------------------------------------
__global__ void kInit() {
    int i = threadIdx.x;
    if (i < 4)  g_acc[i] = 0.0;
    if (i == 4) g_nfg = 0;
    if (i == 5) g_done = 0;
    if (i >= 8 && i < 8 + NB) g_ucnt[i - 8] = 0;
}

// ---------------- kernel A1: geometry only (all anchors) ---------------------
__global__ void kA1(const float* __restrict__ p8, const float* __restrict__ p16,
                    const float* __restrict__ p32, const float* __restrict__ gtb) {
    int b   = blockIdx.y;
    int tid = threadIdx.x;
    int a   = blockIdx.x * blockDim.x + tid;

    __shared__ float sB[NG * 4];
    if (tid < NG * 4) sB[tid] = gtb[b * NG * 4 + tid];
    __syncthreads();

    float softp = 0.f;
    bool  uni = false;
    unsigned interM = 0;

    if (a < NA) {
        const float* P; int HW, loc, w; float s;
        level_of(a, b, p8, p16, p32, &P, &HW, &loc, &s, &w);
        P += loc;
        int ix = loc % w, iy = loc / w;
        float xc = ((float)ix + 0.5f) * s;
        float yc = ((float)iy + 0.5f) * s;
        float r2 = 2.5f * s;

        float cf = P[4 * HW];
        // fast softplus: output-side sum only, rel err ~1e-6 << 1e-3 tol
        softp = fmaxf(cf, 0.f) + __logf(1.f + __expf(-fabsf(cf)));

        int idx = b * NA + a;
        g_cnt[idx] = 0;
        g_gsum[idx] = 0;

        #pragma unroll
        for (int g = 0; g < NG; g++) {
            float cx = sB[g * 4 + 0], cy = sB[g * 4 + 1];
            float gw = sB[g * 4 + 2], gh = sB[g * 4 + 3];
            float gminx = cx - gw * 0.5f, gmaxx = cx + gw * 0.5f;
            float gminy = cy - gh * 0.5f, gmaxy = cy + gh * 0.5f;
            bool inb = (xc - gminx > 0.f) && (gmaxx - xc > 0.f) &&
                       (yc - gminy > 0.f) && (gmaxy - yc > 0.f);
            bool inm = (xc - (cx - r2) > 0.f) && ((cx + r2) - xc > 0.f) &&
                       (yc - (cy - r2) > 0.f) && ((cy + r2) - yc > 0.f);
            if (inb && inm) interM |= (1u << g);
            uni = uni || inb || inm;
        }
    }

    unsigned mask = __ballot_sync(0xffffffffu, uni);
    if (uni) {
        int leader = __ffs(mask) - 1;
        int rank   = __popc(mask & ((1u << (tid & 31)) - 1u));
        int base = 0;
        if ((tid & 31) == leader) base = atomicAdd(&g_ucnt[b], __popc(mask));
        base = __shfl_sync(mask, base, leader);
        g_ulist[b * NA + base + rank] = a | ((int)interM << 16);
    }

    reduce1(softp, 1);
}

// ---------------- kernel A2: heavy math over compacted union list ------------
__global__ void kA2(const float* __restrict__ p8, const float* __restrict__ p16,
                    const float* __restrict__ p32, const float* __restrict__ gtb,
                    const int* __restrict__ gtc) {
    int b   = blockIdx.y;
    int tid = threadIdx.x;
    int i   = blockIdx.x * blockDim.x + tid;

    __shared__ float sB[NG * 4];
    __shared__ int   sC[NG];
    __shared__ int   sSlot[NCLS];
    __shared__ float sD[NG * 256];

    if (tid < NG * 4) sB[tid] = gtb[b * NG * 4 + tid];
    if (tid < NG)     sC[tid] = gtc[b * NG + tid];
    if (tid < NCLS)   sSlot[tid] = -1;
    __syncthreads();
    if (tid == 0) {
        #pragma unroll
        for (int g = 0; g < NG; g++)
            if (sSlot[sC[g]] < 0) sSlot[sC[g]] = g;
    }
    __syncthreads();

    if (i >= g_ucnt[b]) return;

    int packed = g_ulist[b * NA + i];
    int a      = packed & 0xffff;
    unsigned interM = (unsigned)packed >> 16;

    const float* P; int HW, loc, w; float s;
    level_of(a, b, p8, p16, p32, &P, &HW, &loc, &s, &w);
    P += loc;
    int ix = loc % w, iy = loc / w;
    int idx = b * NA + a;
    g_ia[idx] = i;

    // decode (precise: feeds iou -> dyn_k trunc and box loss)
    float px = P[0], py = P[HW], pw = P[2 * HW], ph = P[3 * HW];
    float cf = P[4 * HW];
    float bx = (px + (float)ix) * s;
    float by = (py + (float)iy) * s;
    float bw = expf(pw) * s;
    float bh = expf(ph) * s;
    g_pbox[idx * 4 + 0] = bx; g_pbox[idx * 4 + 1] = by;
    g_pbox[idx * 4 + 2] = bw; g_pbox[idx * 4 + 3] = bh;

    float rr = rsqrtf(1.f + __expf(-cf));   // sqrt(sigmoid(cf))

    float s2 = 0.f;
    #pragma unroll 2
    for (int c8 = 0; c8 < NCLS; c8 += 8) {
        float prod = 1.f;
        #pragma unroll
        for (int j = 0; j < 8; j++) {
            int c = c8 + j;
            float x = P[(5 + c) * HW];
            float p = rr * rsqrtf(1.f + __expf(-x));
            float t = fmaxf(1.f - p, 1e-12f);
            prod *= t;
            int slot = sSlot[c];
            if (slot >= 0)
                sD[slot * 256 + tid] = __logf(fmaxf(p, 1e-12f)) - __logf(t);
        }
        s2 += __log2f(prod);
    }
    float suml1 = s2 * 0.69314718055994531f;

    float areab = bw * bh;
    float bhw = bw * 0.5f, bhh = bh * 0.5f;
    float bestc = 3.402823466e38f;
    int   bestg = 0;
    size_t base = ((size_t)b * NG) * NA + i;

    for (int g = 0; g < NG; g++) {
        float cx = sB[g * 4 + 0], cy = sB[g * 4 + 1];
        float gw = sB[g * 4 + 2], gh = sB[g * 4 + 3];
        int   slot = sSlot[sC[g]];
        float d  = sD[slot * 256 + tid];
        float cls_cost = -(d + suml1);

        float tlx = fmaxf(cx - gw * 0.5f, bx - bhw);
        float tly = fmaxf(cy - gh * 0.5f, by - bhh);
        float brx = fminf(cx + gw * 0.5f, bx + bhw);
        float bry = fminf(cy + gh * 0.5f, by + bhh);
        float iw = fmaxf(brx - tlx, 0.f), ih = fmaxf(bry - tly, 0.f);
        float inter = iw * ih;
        float iou = inter / (gw * gh + areab - inter + 1e-16f);

        float cost = cls_cost - 3.f * __logf(iou + 1e-8f) +
                     (((interM >> g) & 1u) ? 0.f : 100000.f);
        if (cost < bestc) { bestc = cost; bestg = g; }

        g_ci[base + (size_t)g * NA] = make_float2(cost, iou);
    }
    g_best[idx] = bestg;
}

// ---------------- kernel B: split-list 4-warp top-k ---------------------------
// warps 0-1: cost list (stride-64 scan, per-warp tournament)
// warps 2-3: iou list   (stride-64 scan, per-warp tournament)
// phase 2: warp0 merges 20 cost entries || warp2 merges 20 iou entries -> dyn_k
__global__ void kB() {
    const float CSENT = 3.402823466e38f;
    const float ISENT = -1e30f;
    int bg   = blockIdx.x;
    int b    = bg >> 4;
    int tid  = threadIdx.x;          // 128
    int lane = tid & 31, wid = tid >> 5;
    size_t cbase = (size_t)bg * NA;
    int n = g_ucnt[b];

    __shared__ float          slV[64 * 11];     // per-thread sorted lists (own half)
    __shared__ unsigned short slX[64 * 11];
    __shared__ float          sCv[2 * CAND];
    __shared__ int            sCi[2 * CAND];
    __shared__ float          sIv[2 * CAND];
    __shared__ int            sDynk;
    __shared__ int            sWin[CAND];

    if (wid < 2) {
        // ---- cost scan: threads 0..63, stride 64 ----
        float cv[CAND]; unsigned short cx[CAND];
        #pragma unroll
        for (int k = 0; k < CAND; k++) { cv[k] = CSENT; cx[k] = 0; }
        for (int i = tid; i < n; i += 64) {
            int a = g_ulist[b * NA + i] & 0xffff;
            float v = g_ci[cbase + i].x;
            if (v < cv[CAND - 1]) {
                unsigned short id = (unsigned short)a;
                #pragma unroll
                for (int k = 0; k < CAND; k++)
                    if (v < cv[k]) {
                        float tv = cv[k]; cv[k] = v; v = tv;
                        unsigned short ti = cx[k]; cx[k] = id; id = ti;
                    }
            }
        }
        #pragma unroll
        for (int k = 0; k < CAND; k++) { slV[tid * 11 + k] = cv[k]; slX[tid * 11 + k] = cx[k]; }

        // per-warp tournament (min cost, exact index tie-break)
        int cp = 0;
        #pragma unroll
        for (int k = 0; k < CAND; k++) {
            float vc  = slV[tid * 11 + cp];
            int   myi = (int)slX[tid * 11 + cp];
            float mc = vc;
            #pragma unroll
            for (int off = 16; off > 0; off >>= 1)
                mc = fminf(mc, __shfl_xor_sync(0xffffffffu, mc, off));
            int cand = (vc == mc) ? myi : 0x7fffffff;
            #pragma unroll
            for (int off = 16; off > 0; off >>= 1)
                cand = min(cand, __shfl_xor_sync(0xffffffffu, cand, off));
            if (vc == mc && myi == cand) cp++;
            if (lane == 0) { sCv[wid * CAND + k] = mc; sCi[wid * CAND + k] = cand; }
        }
    } else {
        // ---- iou scan: threads 64..127, stride 64 ----
        int lt = tid - 64;
        float iv[CAND];
        #pragma unroll
        for (int k = 0; k < CAND; k++) iv[k] = ISENT;
        for (int i = lt; i < n; i += 64) {
            float v = g_ci[cbase + i].y;
            if (v > iv[CAND - 1]) {
                #pragma unroll
                for (int k = 0; k < CAND; k++)
                    if (v > iv[k]) { float tv = iv[k]; iv[k] = v; v = tv; }
            }
        }
        #pragma unroll
        for (int k = 0; k < CAND; k++) slV[lt * 11 + k] = iv[k];

        // per-warp tournament (max iou, values only)
        int ip = 0;
        #pragma unroll
        for (int k = 0; k < CAND; k++) {
            float vi = slV[lt * 11 + ip];
            float mi = vi;
            #pragma unroll
            for (int off = 16; off > 0; off >>= 1)
                mi = fmaxf(mi, __shfl_xor_sync(0xffffffffu, mi, off));
            unsigned msk = __ballot_sync(0xffffffffu, vi == mi);
            if (lane == (int)(__ffs(msk) - 1)) ip++;
            if (lane == 0) sIv[(wid - 2) * CAND + k] = mi;
        }
    }
    __syncthreads();

    // ---- phase 2 (parallel on warps 0 and 2) ----
    if (wid == 0) {
        float v = (lane < 2 * CAND) ? sCv[lane] : CSENT;
        int   x = (lane < 2 * CAND) ? sCi[lane] : 0x7fffffff;
        #pragma unroll
        for (int k = 0; k < CAND; k++) {
            float mc = v;
            #pragma unroll
            for (int off = 16; off > 0; off >>= 1)
                mc = fminf(mc, __shfl_xor_sync(0xffffffffu, mc, off));
            int cand = (v == mc) ? x : 0x7fffffff;
            #pragma unroll
            for (int off = 16; off > 0; off >>= 1)
                cand = min(cand, __shfl_xor_sync(0xffffffffu, cand, off));
            if (v == mc && x == cand) v = CSENT;
            if (lane == 0) sWin[k] = cand;
        }
    } else if (wid == 2) {
        float v = (lane < 2 * CAND) ? sIv[lane] : ISENT;
        float isum = 0.f;
        #pragma unroll
        for (int k = 0; k < CAND; k++) {
            float mi = v;
            #pragma unroll
            for (int off = 16; off > 0; off >>= 1)
                mi = fmaxf(mi, __shfl_xor_sync(0xffffffffu, mi, off));
            isum += mi;
            unsigned msk = __ballot_sync(0xffffffffu, v == mi);
            if (lane == (int)(__ffs(msk) - 1)) v = ISENT;
        }
        if (lane == 0) {
            int dynk = (int)isum;          // trunc, matches astype(int32)
            sDynk = dynk < 1 ? 1 : dynk;
        }
    }
    __syncthreads();

    if (tid == 0) {
        int dynk = sDynk;
        int g = bg & 15;
        #pragma unroll
        for (int k = 0; k < CAND; k++) {
            if (k < dynk) {
                int idx = b * NA + sWin[k];
                int old = atomicAdd(&g_cnt[idx], 1);
                atomicAdd(&g_gsum[idx], g);
                if (old == 0) {
                    int pos = atomicAdd(&g_nfg, 1);
                    g_list[pos] = idx;
                }
            }
        }
    }
}

// ---------------- fg-only losses + fused final combine ------------------------
__global__ void kLoss(const float* __restrict__ p8, const float* __restrict__ p16,
                      const float* __restrict__ p32, const float* __restrict__ gtb,
                      const int* __restrict__ gtc, float* out) {
    int gid  = blockIdx.x * blockDim.x + threadIdx.x;
    int wi   = gid >> 5;
    int lane = gid & 31;

    float lb = 0.f, lcf = 0.f, lcl = 0.f, nf = 0.f;
    if (wi < g_nfg) {
        int idx = g_list[wi];
        int b = idx / NA, a = idx - b * NA;
        int cnt = g_cnt[idx];
        int gi = (cnt == 1) ? g_gsum[idx] : g_best[idx];
        int ii = g_ia[idx];
        float miou = g_ci[((size_t)(b * NG + gi)) * NA + ii].y;
        int tc = gtc[b * NG + gi];
        const float* P; int HW, loc, w; float s;
        level_of(a, b, p8, p16, p32, &P, &HW, &loc, &s, &w);
        P += loc;

        // 80 classes across 32 lanes; fast BCE (output-side sum, err ~1e-6)
        {
            int c0 = lane, c1 = lane + 32;
            float x0 = P[(5 + c0) * HW];
            float x1 = P[(5 + c1) * HW];
            float t0 = (c0 == tc) ? miou : 0.f;
            float t1 = (c1 == tc) ? miou : 0.f;
            lcl  = fmaxf(x0, 0.f) - x0 * t0 + __logf(1.f + __expf(-fabsf(x0)));
            lcl += fmaxf(x1, 0.f) - x1 * t1 + __logf(1.f + __expf(-fabsf(x1)));
            if (lane < 16) {
                int c2 = lane + 64;
                float x2 = P[(5 + c2) * HW];
                float t2 = (c2 == tc) ? miou : 0.f;
                lcl += fmaxf(x2, 0.f) - x2 * t2 + __logf(1.f + __expf(-fabsf(x2)));
            }
        }

        if (lane == 0) {
            float bx = g_pbox[idx * 4 + 0], by = g_pbox[idx * 4 + 1];
            float bw = g_pbox[idx * 4 + 2], bh = g_pbox[idx * 4 + 3];
            const float* gb = gtb + (b * NG + gi) * 4;
            float cx = gb[0], cy = gb[1], gw = gb[2], gh = gb[3];
            float tlx = fmaxf(bx - bw * 0.5f, cx - gw * 0.5f);
            float tly = fmaxf(by - bh * 0.5f, cy - gh * 0.5f);
            float brx = fminf(bx + bw * 0.5f, cx + gw * 0.5f);
            float bry = fminf(by + bh * 0.5f, cy + gh * 0.5f);
            float iw = fmaxf(brx - tlx, 0.f), ih = fmaxf(bry - tly, 0.f);
            float inter = iw * ih;
            float ioue = inter / (bw * bh + gw * gh - inter + 1e-16f);
            lb = 1.f - ioue * ioue;
            nf = 1.f;
            lcf = -P[4 * HW];   // -x*fg term; softplus summed in kA1
        }
    }
    reduce4(lb, lcf, lcl, nf);

    // last-block-done: fold kFinal in
    if (threadIdx.x == 0) {
        __threadfence();
        int t = atomicAdd(&g_done, 1);
        if (t == (int)gridDim.x - 1) {
            g_done = 0;
            double nfg = g_acc[3];
            if (nfg < 1.0) nfg = 1.0;
            out[0] = (float)((5.0 * g_acc[0] + g_acc[1] + g_acc[2]) / nfg);
        }
    }
}

// ---------------- launcher -----------------------------------------------------
extern "C" void kernel_launch(void* const* d_in, const int* in_sizes, int n_in,
                              void* d_out, int out_size) {
    const float* p8  = (const float*)d_in[0];
    const float* p16 = (const float*)d_in[1];
    const float* p32 = (const float*)d_in[2];
    const float* gtb = (const float*)d_in[3];
    const int*   gtc = (const int*)d_in[4];
    (void)in_sizes; (void)n_in; (void)out_size;

    dim3 grid((NA + 255) / 256, NB);
    kInit<<<1, 64>>>();
    kA1<<<grid, 256>>>(p8, p16, p32, gtb);
    kA2<<<grid, 256>>>(p8, p16, p32, gtb, gtc);
    kB<<<NB * NG, 128>>>();
    kLoss<<<(MAXFG * 32 + 255) / 256, 256>>>(p8, p16, p32, gtb, gtc, (float*)d_out);
}

// round 14
// speedup vs baseline: 1.6227x; 1.6227x over previous
#include <cuda_runtime.h>
#include <math.h>
#include <stdint.h>

#define NB 32
#define NG 16
#define NA 8400
#define NCLS 80
#define CAND 10
#define MAXFG (NB * NG * CAND)

// ---------------- scratch (device globals) ----------------------------------
__device__ float2        g_ci  [(size_t)NB * NG * NA];   // (cost, iou), indexed by COMPACT i
__device__ float         g_pbox[(size_t)NB * NA * 4];
__device__ int           g_ia  [(size_t)NB * NA];        // anchor -> compact index
__device__ int           g_best[(size_t)NB * NA];
__device__ int           g_cnt [(size_t)NB * NA];
__device__ int           g_gsum[(size_t)NB * NA];
__device__ int           g_ulist[(size_t)NB * NA];       // per-b packed: a | (interM<<16)
__device__ int           g_ucnt[NB];
__device__ int           g_list[MAXFG];
__device__ int           g_nfg;
__device__ double        g_acc[4];   // loss_box, loss_conf, loss_cls, n_fg

static __device__ __forceinline__ void level_of(int a, int b,
                                                const float* p8, const float* p16, const float* p32,
                                                const float** P, int* HW, int* loc, float* s, int* w) {
    if (a < 6400)      { *P = p8  + (size_t)b * 85 * 6400; *HW = 6400; *loc = a;        *s = 8.f;  *w = 80; }
    else if (a < 8000) { *P = p16 + (size_t)b * 85 * 1600; *HW = 1600; *loc = a - 6400; *s = 16.f; *w = 40; }
    else               { *P = p32 + (size_t)b * 85 * 400;  *HW = 400;  *loc = a - 8000; *s = 32.f; *w = 20; }
}

static __device__ __forceinline__ void reduce1(float v, int slot) {
    int tid = threadIdx.x, lane = tid & 31, wid = tid >> 5;
    #pragma unroll
    for (int off = 16; off > 0; off >>= 1) v += __shfl_down_sync(0xffffffffu, v, off);
    __shared__ float sw[8];
    if (lane == 0) sw[wid] = v;
    __syncthreads();
    if (tid == 0) {
        float a0 = 0.f;
        #pragma unroll
        for (int i = 0; i < 8; i++) a0 += sw[i];
        atomicAdd(&g_acc[slot], (double)a0);
    }
}

static __device__ __forceinline__ void reduce4(float v0, float v1, float v2, float v3) {
    int tid = threadIdx.x, lane = tid & 31, wid = tid >> 5;
    #pragma unroll
    for (int off = 16; off > 0; off >>= 1) {
        v0 += __shfl_down_sync(0xffffffffu, v0, off);
        v1 += __shfl_down_sync(0xffffffffu, v1, off);
        v2 += __shfl_down_sync(0xffffffffu, v2, off);
        v3 += __shfl_down_sync(0xffffffffu, v3, off);
    }
    __shared__ float sw[8][4];
    if (lane == 0) { sw[wid][0] = v0; sw[wid][1] = v1; sw[wid][2] = v2; sw[wid][3] = v3; }
    __syncthreads();
    if (tid == 0) {
        float a0 = 0, a1 = 0, a2 = 0, a3 = 0;
        #pragma unroll
        for (int i = 0; i < 8; i++) { a0 += sw[i][0]; a1 += sw[i][1]; a2 += sw[i][2]; a3 += sw[i][3]; }
        if (a0 != 0.f) atomicAdd(&g_acc[0], (double)a0);
        if (a1 != 0.f) atomicAdd(&g_acc[1], (double)a1);
        if (a2 != 0.f) atomicAdd(&g_acc[2], (double)a2);
        if (a3 != 0.f) atomicAdd(&g_acc[3], (double)a3);
    }
}

// ---------------- init --------------------------------------------------------
__global__ void kInit() {
    int i = threadIdx.x;
    if (i < 4)  g_acc[i] = 0.0;
    if (i == 4) g_nfg = 0;
    if (i >= 8 && i < 8 + NB) g_ucnt[i - 8] = 0;
}

// ---------------- kernel A1: geometry only (all anchors) ---------------------
__global__ void kA1(const float* __restrict__ p8, const float* __restrict__ p16,
                    const float* __restrict__ p32, const float* __restrict__ gtb) {
    int b   = blockIdx.y;
    int tid = threadIdx.x;
    int a   = blockIdx.x * blockDim.x + tid;

    __shared__ float sB[NG * 4];
    if (tid < NG * 4) sB[tid] = gtb[b * NG * 4 + tid];
    __syncthreads();

    float softp = 0.f;
    bool  uni = false;
    unsigned interM = 0;

    if (a < NA) {
        const float* P; int HW, loc, w; float s;
        level_of(a, b, p8, p16, p32, &P, &HW, &loc, &s, &w);
        P += loc;
        int ix = loc % w, iy = loc / w;
        float xc = ((float)ix + 0.5f) * s;
        float yc = ((float)iy + 0.5f) * s;
        float r2 = 2.5f * s;

        float cf = P[4 * HW];
        softp = fmaxf(cf, 0.f) + log1pf(expf(-fabsf(cf)));   // precise: feeds output

        int idx = b * NA + a;
        g_cnt[idx] = 0;
        g_gsum[idx] = 0;

        #pragma unroll
        for (int g = 0; g < NG; g++) {
            float cx = sB[g * 4 + 0], cy = sB[g * 4 + 1];
            float gw = sB[g * 4 + 2], gh = sB[g * 4 + 3];
            float gminx = cx - gw * 0.5f, gmaxx = cx + gw * 0.5f;
            float gminy = cy - gh * 0.5f, gmaxy = cy + gh * 0.5f;
            bool inb = (xc - gminx > 0.f) && (gmaxx - xc > 0.f) &&
                       (yc - gminy > 0.f) && (gmaxy - yc > 0.f);
            bool inm = (xc - (cx - r2) > 0.f) && ((cx + r2) - xc > 0.f) &&
                       (yc - (cy - r2) > 0.f) && ((cy + r2) - yc > 0.f);
            if (inb && inm) interM |= (1u << g);
            uni = uni || inb || inm;
        }
    }

    // warp-aggregated append to per-image union list
    unsigned mask = __ballot_sync(0xffffffffu, uni);
    if (uni) {
        int leader = __ffs(mask) - 1;
        int rank   = __popc(mask & ((1u << (tid & 31)) - 1u));
        int base = 0;
        if ((tid & 31) == leader) base = atomicAdd(&g_ucnt[b], __popc(mask));
        base = __shfl_sync(mask, base, leader);
        g_ulist[b * NA + base + rank] = a | ((int)interM << 16);
    }

    reduce1(softp, 1);
}

// ---------------- kernel A2: heavy math over compacted union list ------------
__global__ void kA2(const float* __restrict__ p8, const float* __restrict__ p16,
                    const float* __restrict__ p32, const float* __restrict__ gtb,
                    const int* __restrict__ gtc) {
    int b   = blockIdx.y;
    int tid = threadIdx.x;
    int i   = blockIdx.x * blockDim.x + tid;

    __shared__ float sB[NG * 4];
    __shared__ int   sC[NG];
    __shared__ int   sSlot[NCLS];          // class -> g-slot (-1 none)
    __shared__ float sD[NG * 256];         // per-thread d for each used slot

    if (tid < NG * 4) sB[tid] = gtb[b * NG * 4 + tid];
    if (tid < NG)     sC[tid] = gtc[b * NG + tid];
    if (tid < NCLS)   sSlot[tid] = -1;
    __syncthreads();
    if (tid == 0) {
        #pragma unroll
        for (int g = 0; g < NG; g++)
            if (sSlot[sC[g]] < 0) sSlot[sC[g]] = g;
    }
    __syncthreads();

    if (i >= g_ucnt[b]) return;

    int packed = g_ulist[b * NA + i];
    int a      = packed & 0xffff;
    unsigned interM = (unsigned)packed >> 16;

    const float* P; int HW, loc, w; float s;
    level_of(a, b, p8, p16, p32, &P, &HW, &loc, &s, &w);
    P += loc;
    int ix = loc % w, iy = loc / w;
    int idx = b * NA + a;
    g_ia[idx] = i;

    // decode (precise: feeds iou -> dyn_k and box loss)
    float px = P[0], py = P[HW], pw = P[2 * HW], ph = P[3 * HW];
    float cf = P[4 * HW];
    float bx = (px + (float)ix) * s;
    float by = (py + (float)iy) * s;
    float bw = expf(pw) * s;
    float bh = expf(ph) * s;
    g_pbox[idx * 4 + 0] = bx; g_pbox[idx * 4 + 1] = by;
    g_pbox[idx * 4 + 2] = bw; g_pbox[idx * 4 + 3] = bh;

    float rr = rsqrtf(1.f + __expf(-cf));   // sqrt(sigmoid(cf))

    // suml1 = sum_c log(1-p_c) with oct-grouped logs; stash d = log(p)-log(1-p)
    float s2 = 0.f;
    #pragma unroll 2
    for (int c8 = 0; c8 < NCLS; c8 += 8) {
        float prod = 1.f;
        #pragma unroll
        for (int j = 0; j < 8; j++) {
            int c = c8 + j;
            float x = P[(5 + c) * HW];
            float p = rr * rsqrtf(1.f + __expf(-x));
            float t = fmaxf(1.f - p, 1e-12f);
            prod *= t;
            int slot = sSlot[c];
            if (slot >= 0)
                sD[slot * 256 + tid] = __logf(fmaxf(p, 1e-12f)) - __logf(t);
        }
        s2 += __log2f(prod);
    }
    float suml1 = s2 * 0.69314718055994531f;

    float areab = bw * bh;
    float bhw = bw * 0.5f, bhh = bh * 0.5f;
    float bestc = 3.402823466e38f;
    int   bestg = 0;
    size_t base = ((size_t)b * NG) * NA + i;   // compact-i indexed planes

    for (int g = 0; g < NG; g++) {
        float cx = sB[g * 4 + 0], cy = sB[g * 4 + 1];
        float gw = sB[g * 4 + 2], gh = sB[g * 4 + 3];
        int   slot = sSlot[sC[g]];
        float d  = sD[slot * 256 + tid];
        float cls_cost = -(d + suml1);

        float tlx = fmaxf(cx - gw * 0.5f, bx - bhw);
        float tly = fmaxf(cy - gh * 0.5f, by - bhh);
        float brx = fminf(cx + gw * 0.5f, bx + bhw);
        float bry = fminf(cy + gh * 0.5f, by + bhh);
        float iw = fmaxf(brx - tlx, 0.f), ih = fmaxf(bry - tly, 0.f);
        float inter = iw * ih;
        float iou = inter / (gw * gh + areab - inter + 1e-16f);

        float cost = cls_cost - 3.f * __logf(iou + 1e-8f) +
                     (((interM >> g) & 1u) ? 0.f : 100000.f);
        if (cost < bestc) { bestc = cost; bestg = g; }

        g_ci[base + (size_t)g * NA] = make_float2(cost, iou);
    }
    g_best[idx] = bestg;
}

// ---------------- kernel B: T=256, f32 extraction, exact tie-break -----------
__global__ void kB() {
    const int T = 256;
    const int NW = 8;
    const float CSENT = 3.402823466e38f;
    const float ISENT = -1e30f;
    int bg  = blockIdx.x;          // b*16 + g
    int b   = bg >> 4;
    int tid = threadIdx.x;
    int lane = tid & 31, wid = tid >> 5;
    size_t cbase = (size_t)bg * NA;   // compact-i indexed

    float cv[CAND], iv[CAND];
    unsigned short cix[CAND];
    #pragma unroll
    for (int k = 0; k < CAND; k++) { cv[k] = CSENT; iv[k] = ISENT; cix[k] = 0; }

    int n = g_ucnt[b];
    for (int i = tid; i < n; i += T) {
        int a = g_ulist[b * NA + i] & 0xffff;
        float2 ci = g_ci[cbase + i];   // coalesced
        // min-cost list: strict < keeps encounter order (= index asc) for ties
        if (ci.x < cv[CAND - 1]) {
            float v = ci.x; unsigned short id = (unsigned short)a;
            #pragma unroll
            for (int k = 0; k < CAND; k++)
                if (v < cv[k]) {
                    float tv = cv[k]; cv[k] = v; v = tv;
                    unsigned short ti = cix[k]; cix[k] = id; id = ti;
                }
        }
        // max-iou list (values only)
        if (ci.y > iv[CAND - 1]) {
            float v = ci.y;
            #pragma unroll
            for (int k = 0; k < CAND; k++)
                if (v > iv[k]) { float tv = iv[k]; iv[k] = v; v = tv; }
        }
    }

    // dump lists to smem (stride 11 -> conflict-free)
    __shared__ float          slC[T * 11], slI[T * 11];
    __shared__ unsigned short slX[T * 11];
    __shared__ float          smCw[NW * CAND], smIw[NW * CAND];
    __shared__ int            smCi[NW * CAND];
    #pragma unroll
    for (int k = 0; k < CAND; k++) {
        slC[tid * 11 + k] = cv[k];
        slI[tid * 11 + k] = iv[k];
        slX[tid * 11 + k] = cix[k];
    }

    // per-warp extraction: 10 rounds, f32 butterflies
    {
        int cp = 0, ip = 0;
        #pragma unroll 1
        for (int k = 0; k < CAND; k++) {
            // iou (max, values only; consume lowest tied lane)
            float viou = slI[tid * 11 + ip];
            float mi = viou;
            #pragma unroll
            for (int off = 16; off > 0; off >>= 1)
                mi = fmaxf(mi, __shfl_xor_sync(0xffffffffu, mi, off));
            unsigned msk = __ballot_sync(0xffffffffu, viou == mi);
            if (lane == (int)(__ffs(msk) - 1)) ip++;

            // cost (min, exact (value, index) tie-break)
            float vc = slC[tid * 11 + cp];
            int   myi = (int)slX[tid * 11 + cp];
            float mc = vc;
            #pragma unroll
            for (int off = 16; off > 0; off >>= 1)
                mc = fminf(mc, __shfl_xor_sync(0xffffffffu, mc, off));
            int cand = (vc == mc) ? myi : 0x7fffffff;
            #pragma unroll
            for (int off = 16; off > 0; off >>= 1)
                cand = min(cand, __shfl_xor_sync(0xffffffffu, cand, off));
            if (vc == mc && myi == cand) cp++;

            if (lane == 0) {
                smIw[wid * CAND + k] = mi;
                smCw[wid * CAND + k] = mc;
                smCi[wid * CAND + k] = cand;
            }
        }
    }
    __syncthreads();

    // final merge over 8*10 = 80 entries by warp0 (3 regs/lane)
    if (wid == 0) {
        float c0 = smCw[lane];
        float c1 = smCw[32 + lane];
        float c2 = (lane < NW * CAND - 64) ? smCw[64 + lane] : CSENT;
        int   x0 = smCi[lane];
        int   x1 = smCi[32 + lane];
        int   x2 = (lane < NW * CAND - 64) ? smCi[64 + lane] : 0x7fffffff;
        float i0 = smIw[lane];
        float i1 = smIw[32 + lane];
        float i2 = (lane < NW * CAND - 64) ? smIw[64 + lane] : ISENT;

        float isum = 0.f;
        int   cwin[CAND];
        #pragma unroll
        for (int k = 0; k < CAND; k++) {
            // iou max round
            float mi = fmaxf(fmaxf(i0, i1), i2);
            #pragma unroll
            for (int off = 16; off > 0; off >>= 1)
                mi = fmaxf(mi, __shfl_xor_sync(0xffffffffu, mi, off));
            isum += mi;
            unsigned m0 = __ballot_sync(0xffffffffu, i0 == mi);
            if (m0) { if (lane == (int)(__ffs(m0) - 1)) i0 = ISENT; }
            else {
                unsigned m1 = __ballot_sync(0xffffffffu, i1 == mi);
                if (m1) { if (lane == (int)(__ffs(m1) - 1)) i1 = ISENT; }
                else {
                    unsigned m2 = __ballot_sync(0xffffffffu, i2 == mi);
                    if (lane == (int)(__ffs(m2) - 1)) i2 = ISENT;
                }
            }

            // cost min round with exact index tie-break
            float mc = fminf(fminf(c0, c1), c2);
            #pragma unroll
            for (int off = 16; off > 0; off >>= 1)
                mc = fminf(mc, __shfl_xor_sync(0xffffffffu, mc, off));
            int cand = min(min((c0 == mc) ? x0 : 0x7fffffff,
                               (c1 == mc) ? x1 : 0x7fffffff),
                               (c2 == mc) ? x2 : 0x7fffffff);
            #pragma unroll
            for (int off = 16; off > 0; off >>= 1)
                cand = min(cand, __shfl_xor_sync(0xffffffffu, cand, off));
            if (c0 == mc && x0 == cand) c0 = CSENT;
            else if (c1 == mc && x1 == cand) c1 = CSENT;
            else if (c2 == mc && x2 == cand) c2 = CSENT;
            cwin[k] = cand;
        }

        if (lane == 0) {
            int dynk = (int)isum;          // trunc, matches astype(int32)
            if (dynk < 1) dynk = 1;
            int g = bg & 15;
            #pragma unroll
            for (int k = 0; k < CAND; k++) {
                if (k < dynk) {
                    int idx = b * NA + cwin[k];
                    int old = atomicAdd(&g_cnt[idx], 1);
                    atomicAdd(&g_gsum[idx], g);
                    if (old == 0) {
                        int pos = atomicAdd(&g_nfg, 1);
                        g_list[pos] = idx;
                    }
                }
            }
        }
    }
}

// ---------------- fg-only losses: warp per fg entry --------------------------
__global__ void kLoss(const float* __restrict__ p8, const float* __restrict__ p16,
                      const float* __restrict__ p32, const float* __restrict__ gtb,
                      const int* __restrict__ gtc) {
    int gid  = blockIdx.x * blockDim.x + threadIdx.x;
    int wi   = gid >> 5;
    int lane = gid & 31;

    float lb = 0.f, lcf = 0.f, lcl = 0.f, nf = 0.f;
    if (wi < g_nfg) {
        int idx = g_list[wi];
        int b = idx / NA, a = idx - b * NA;
        int cnt = g_cnt[idx];
        int gi = (cnt == 1) ? g_gsum[idx] : g_best[idx];
        int ii = g_ia[idx];
        float miou = g_ci[((size_t)(b * NG + gi)) * NA + ii].y;
        int tc = gtc[b * NG + gi];
        const float* P; int HW, loc, w; float s;
        level_of(a, b, p8, p16, p32, &P, &HW, &loc, &s, &w);
        P += loc;

        // 80 classes across 32 lanes (precise math: feeds output)
        {
            int c0 = lane, c1 = lane + 32;
            float x0 = P[(5 + c0) * HW];
            float x1 = P[(5 + c1) * HW];
            float t0 = (c0 == tc) ? miou : 0.f;
            float t1 = (c1 == tc) ? miou : 0.f;
            lcl  = fmaxf(x0, 0.f) - x0 * t0 + log1pf(expf(-fabsf(x0)));
            lcl += fmaxf(x1, 0.f) - x1 * t1 + log1pf(expf(-fabsf(x1)));
            if (lane < 16) {
                int c2 = lane + 64;
                float x2 = P[(5 + c2) * HW];
                float t2 = (c2 == tc) ? miou : 0.f;
                lcl += fmaxf(x2, 0.f) - x2 * t2 + log1pf(expf(-fabsf(x2)));
            }
        }

        if (lane == 0) {
            float bx = g_pbox[idx * 4 + 0], by = g_pbox[idx * 4 + 1];
            float bw = g_pbox[idx * 4 + 2], bh = g_pbox[idx * 4 + 3];
            const float* gb = gtb + (b * NG + gi) * 4;
            float cx = gb[0], cy = gb[1], gw = gb[2], gh = gb[3];
            float tlx = fmaxf(bx - bw * 0.5f, cx - gw * 0.5f);
            float tly = fmaxf(by - bh * 0.5f, cy - gh * 0.5f);
            float brx = fminf(bx + bw * 0.5f, cx + gw * 0.5f);
            float bry = fminf(by + bh * 0.5f, cy + gh * 0.5f);
            float iw = fmaxf(brx - tlx, 0.f), ih = fmaxf(bry - tly, 0.f);
            float inter = iw * ih;
            float ioue = inter / (bw * bh + gw * gh - inter + 1e-16f);
            lb = 1.f - ioue * ioue;
            nf = 1.f;
            lcf = -P[4 * HW];   // -x*fg term; softplus summed in kA1
        }
    }
    reduce4(lb, lcf, lcl, nf);
}

// ---------------- final combine ----------------------------------------------
__global__ void kFinal(float* out) {
    double nf = g_acc[3];
    if (nf < 1.0) nf = 1.0;
    out[0] = (float)((5.0 * g_acc[0] + g_acc[1] + g_acc[2]) / nf);
}

// ---------------- launcher -----------------------------------------------------
extern "C" void kernel_launch(void* const* d_in, const int* in_sizes, int n_in,
                              void* d_out, int out_size) {
    const float* p8  = (const float*)d_in[0];
    const float* p16 = (const float*)d_in[1];
    const float* p32 = (const float*)d_in[2];
    const float* gtb = (const float*)d_in[3];
    const int*   gtc = (const int*)d_in[4];
    (void)in_sizes; (void)n_in; (void)out_size;

    dim3 grid((NA + 255) / 256, NB);
    kInit<<<1, 64>>>();
    kA1<<<grid, 256>>>(p8, p16, p32, gtb);
    kA2<<<grid, 256>>>(p8, p16, p32, gtb, gtc);
    kB<<<NB * NG, 256>>>();
    kLoss<<<(MAXFG * 32 + 255) / 256, 256>>>(p8, p16, p32, gtb, gtc);
    kFinal<<<1, 1>>>((float*)d_out);
}

// round 15
// speedup vs baseline: 1.6246x; 1.0011x over previous
#include <cuda_runtime.h>
#include <math.h>
#include <stdint.h>

#define NB 32
#define NG 16
#define NA 8400
#define NCLS 80
#define CAND 10
#define MAXFG (NB * NG * CAND)
#define LOSS_BLOCKS ((MAXFG * 32 + 255) / 256)

// ---------------- scratch (device globals; zero-initialized at load,
// re-zeroed by kLoss's last block for the next invocation) -------------------
__device__ float2        g_ci  [(size_t)NB * NG * NA];   // (cost, iou), COMPACT i indexed
__device__ float         g_pbox[(size_t)NB * NA * 4];
__device__ int           g_ia  [(size_t)NB * NA];        // anchor -> compact index
__device__ int           g_best[(size_t)NB * NA];
__device__ int           g_cnt [(size_t)NB * NA];
__device__ int           g_gsum[(size_t)NB * NA];
__device__ int           g_ulist[(size_t)NB * NA];       // per-b packed: a | (interM<<16)
__device__ int           g_ucnt[NB];
__device__ int           g_list[MAXFG];
__device__ int           g_nfg;
__device__ int           g_done;
__device__ double        g_acc[4];   // loss_box, loss_conf, loss_cls, n_fg

static __device__ __forceinline__ void level_of(int a, int b,
                                                const float* p8, const float* p16, const float* p32,
                                                const float** P, int* HW, int* loc, float* s, int* w) {
    if (a < 6400)      { *P = p8  + (size_t)b * 85 * 6400; *HW = 6400; *loc = a;        *s = 8.f;  *w = 80; }
    else if (a < 8000) { *P = p16 + (size_t)b * 85 * 1600; *HW = 1600; *loc = a - 6400; *s = 16.f; *w = 40; }
    else               { *P = p32 + (size_t)b * 85 * 400;  *HW = 400;  *loc = a - 8000; *s = 32.f; *w = 20; }
}

static __device__ __forceinline__ void reduce1(float v, int slot) {
    int tid = threadIdx.x, lane = tid & 31, wid = tid >> 5;
    #pragma unroll
    for (int off = 16; off > 0; off >>= 1) v += __shfl_down_sync(0xffffffffu, v, off);
    __shared__ float sw[8];
    if (lane == 0) sw[wid] = v;
    __syncthreads();
    if (tid == 0) {
        float a0 = 0.f;
        #pragma unroll
        for (int i = 0; i < 8; i++) a0 += sw[i];
        atomicAdd(&g_acc[slot], (double)a0);
    }
}

static __device__ __forceinline__ void reduce4(float v0, float v1, float v2, float v3) {
    int tid = threadIdx.x, lane = tid & 31, wid = tid >> 5;
    #pragma unroll
    for (int off = 16; off > 0; off >>= 1) {
        v0 += __shfl_down_sync(0xffffffffu, v0, off);
        v1 += __shfl_down_sync(0xffffffffu, v1, off);
        v2 += __shfl_down_sync(0xffffffffu, v2, off);
        v3 += __shfl_down_sync(0xffffffffu, v3, off);
    }
    __shared__ float sw[8][4];
    if (lane == 0) { sw[wid][0] = v0; sw[wid][1] = v1; sw[wid][2] = v2; sw[wid][3] = v3; }
    __syncthreads();
    if (tid == 0) {
        float a0 = 0, a1 = 0, a2 = 0, a3 = 0;
        #pragma unroll
        for (int i = 0; i < 8; i++) { a0 += sw[i][0]; a1 += sw[i][1]; a2 += sw[i][2]; a3 += sw[i][3]; }
        if (a0 != 0.f) atomicAdd(&g_acc[0], (double)a0);
        if (a1 != 0.f) atomicAdd(&g_acc[1], (double)a1);
        if (a2 != 0.f) atomicAdd(&g_acc[2], (double)a2);
        if (a3 != 0.f) atomicAdd(&g_acc[3], (double)a3);
    }
}

// ---------------- kernel A1: geometry only (all anchors) ---------------------
__global__ void kA1(const float* __restrict__ p8, const float* __restrict__ p16,
                    const float* __restrict__ p32, const float* __restrict__ gtb) {
    int b   = blockIdx.y;
    int tid = threadIdx.x;
    int a   = blockIdx.x * blockDim.x + tid;

    __shared__ float sB[NG * 4];
    if (tid < NG * 4) sB[tid] = gtb[b * NG * 4 + tid];
    __syncthreads();

    float softp = 0.f;
    bool  uni = false;
    unsigned interM = 0;

    if (a < NA) {
        const float* P; int HW, loc, w; float s;
        level_of(a, b, p8, p16, p32, &P, &HW, &loc, &s, &w);
        P += loc;
        int ix = loc % w, iy = loc / w;
        float xc = ((float)ix + 0.5f) * s;
        float yc = ((float)iy + 0.5f) * s;
        float r2 = 2.5f * s;

        float cf = P[4 * HW];
        // fast softplus: output-side sum; verified identical rel_err in R13
        softp = fmaxf(cf, 0.f) + __logf(1.f + __expf(-fabsf(cf)));

        int idx = b * NA + a;
        g_cnt[idx] = 0;
        g_gsum[idx] = 0;

        #pragma unroll
        for (int g = 0; g < NG; g++) {
            float cx = sB[g * 4 + 0], cy = sB[g * 4 + 1];
            float gw = sB[g * 4 + 2], gh = sB[g * 4 + 3];
            float gminx = cx - gw * 0.5f, gmaxx = cx + gw * 0.5f;
            float gminy = cy - gh * 0.5f, gmaxy = cy + gh * 0.5f;
            bool inb = (xc - gminx > 0.f) && (gmaxx - xc > 0.f) &&
                       (yc - gminy > 0.f) && (gmaxy - yc > 0.f);
            bool inm = (xc - (cx - r2) > 0.f) && ((cx + r2) - xc > 0.f) &&
                       (yc - (cy - r2) > 0.f) && ((cy + r2) - yc > 0.f);
            if (inb && inm) interM |= (1u << g);
            uni = uni || inb || inm;
        }
    }

    // warp-aggregated append to per-image union list
    unsigned mask = __ballot_sync(0xffffffffu, uni);
    if (uni) {
        int leader = __ffs(mask) - 1;
        int rank   = __popc(mask & ((1u << (tid & 31)) - 1u));
        int base = 0;
        if ((tid & 31) == leader) base = atomicAdd(&g_ucnt[b], __popc(mask));
        base = __shfl_sync(mask, base, leader);
        g_ulist[b * NA + base + rank] = a | ((int)interM << 16);
    }

    reduce1(softp, 1);
}

// ---------------- kernel A2: heavy math over compacted union list ------------
__global__ void kA2(const float* __restrict__ p8, const float* __restrict__ p16,
                    const float* __restrict__ p32, const float* __restrict__ gtb,
                    const int* __restrict__ gtc) {
    int b   = blockIdx.y;
    int tid = threadIdx.x;
    int i   = blockIdx.x * blockDim.x + tid;

    // early exit BEFORE smem setup: ~95% of blocks have no work
    int n = g_ucnt[b];
    if (blockIdx.x * blockDim.x >= n) return;

    __shared__ float sB[NG * 4];
    __shared__ int   sC[NG];
    __shared__ int   sSlot[NCLS];          // class -> g-slot (-1 none)
    __shared__ float sD[NG * 256];         // per-thread d for each used slot

    if (tid < NG * 4) sB[tid] = gtb[b * NG * 4 + tid];
    if (tid < NG)     sC[tid] = gtc[b * NG + tid];
    if (tid < NCLS)   sSlot[tid] = -1;
    __syncthreads();
    if (tid == 0) {
        #pragma unroll
        for (int g = 0; g < NG; g++)
            if (sSlot[sC[g]] < 0) sSlot[sC[g]] = g;
    }
    __syncthreads();

    if (i >= n) return;

    int packed = g_ulist[b * NA + i];
    int a      = packed & 0xffff;
    unsigned interM = (unsigned)packed >> 16;

    const float* P; int HW, loc, w; float s;
    level_of(a, b, p8, p16, p32, &P, &HW, &loc, &s, &w);
    P += loc;
    int ix = loc % w, iy = loc / w;
    int idx = b * NA + a;
    g_ia[idx] = i;

    // decode (precise: feeds iou -> dyn_k and box loss)
    float px = P[0], py = P[HW], pw = P[2 * HW], ph = P[3 * HW];
    float cf = P[4 * HW];
    float bx = (px + (float)ix) * s;
    float by = (py + (float)iy) * s;
    float bw = expf(pw) * s;
    float bh = expf(ph) * s;
    g_pbox[idx * 4 + 0] = bx; g_pbox[idx * 4 + 1] = by;
    g_pbox[idx * 4 + 2] = bw; g_pbox[idx * 4 + 3] = bh;

    float rr = rsqrtf(1.f + __expf(-cf));   // sqrt(sigmoid(cf))

    // suml1 = sum_c log(1-p_c) with oct-grouped logs; stash d = log(p)-log(1-p)
    float s2 = 0.f;
    #pragma unroll 2
    for (int c8 = 0; c8 < NCLS; c8 += 8) {
        float prod = 1.f;
        #pragma unroll
        for (int j = 0; j < 8; j++) {
            int c = c8 + j;
            float x = P[(5 + c) * HW];
            float p = rr * rsqrtf(1.f + __expf(-x));
            float t = fmaxf(1.f - p, 1e-12f);
            prod *= t;
            int slot = sSlot[c];
            if (slot >= 0)
                sD[slot * 256 + tid] = __logf(fmaxf(p, 1e-12f)) - __logf(t);
        }
        s2 += __log2f(prod);
    }
    float suml1 = s2 * 0.69314718055994531f;

    float areab = bw * bh;
    float bhw = bw * 0.5f, bhh = bh * 0.5f;
    float bestc = 3.402823466e38f;
    int   bestg = 0;
    size_t base = ((size_t)b * NG) * NA + i;   // compact-i indexed planes

    for (int g = 0; g < NG; g++) {
        float cx = sB[g * 4 + 0], cy = sB[g * 4 + 1];
        float gw = sB[g * 4 + 2], gh = sB[g * 4 + 3];
        int   slot = sSlot[sC[g]];
        float d  = sD[slot * 256 + tid];
        float cls_cost = -(d + suml1);

        float tlx = fmaxf(cx - gw * 0.5f, bx - bhw);
        float tly = fmaxf(cy - gh * 0.5f, by - bhh);
        float brx = fminf(cx + gw * 0.5f, bx + bhw);
        float bry = fminf(cy + gh * 0.5f, by + bhh);
        float iw = fmaxf(brx - tlx, 0.f), ih = fmaxf(bry - tly, 0.f);
        float inter = iw * ih;
        float iou = inter / (gw * gh + areab - inter + 1e-16f);

        float cost = cls_cost - 3.f * __logf(iou + 1e-8f) +
                     (((interM >> g) & 1u) ? 0.f : 100000.f);
        if (cost < bestc) { bestc = cost; bestg = g; }

        g_ci[base + (size_t)g * NA] = make_float2(cost, iou);
    }
    g_best[idx] = bestg;
}

// ---------------- kernel B: T=256, f32 extraction, exact tie-break -----------
__global__ void kB() {
    const int T = 256;
    const int NW = 8;
    const float CSENT = 3.402823466e38f;
    const float ISENT = -1e30f;
    int bg  = blockIdx.x;          // b*16 + g
    int b   = bg >> 4;
    int tid = threadIdx.x;
    int lane = tid & 31, wid = tid >> 5;
    size_t cbase = (size_t)bg * NA;   // compact-i indexed

    float cv[CAND], iv[CAND];
    unsigned short cix[CAND];
    #pragma unroll
    for (int k = 0; k < CAND; k++) { cv[k] = CSENT; iv[k] = ISENT; cix[k] = 0; }

    int n = g_ucnt[b];
    for (int i = tid; i < n; i += T) {
        int a = g_ulist[b * NA + i] & 0xffff;
        float2 ci = g_ci[cbase + i];   // coalesced
        // min-cost list: strict < keeps encounter order (= index asc) for ties
        if (ci.x < cv[CAND - 1]) {
            float v = ci.x; unsigned short id = (unsigned short)a;
            #pragma unroll
            for (int k = 0; k < CAND; k++)
                if (v < cv[k]) {
                    float tv = cv[k]; cv[k] = v; v = tv;
                    unsigned short ti = cix[k]; cix[k] = id; id = ti;
                }
        }
        // max-iou list (values only)
        if (ci.y > iv[CAND - 1]) {
            float v = ci.y;
            #pragma unroll
            for (int k = 0; k < CAND; k++)
                if (v > iv[k]) { float tv = iv[k]; iv[k] = v; v = tv; }
        }
    }

    // dump lists to smem (stride 11 -> conflict-free)
    __shared__ float          slC[T * 11], slI[T * 11];
    __shared__ unsigned short slX[T * 11];
    __shared__ float          smCw[NW * CAND], smIw[NW * CAND];
    __shared__ int            smCi[NW * CAND];
    #pragma unroll
    for (int k = 0; k < CAND; k++) {
        slC[tid * 11 + k] = cv[k];
        slI[tid * 11 + k] = iv[k];
        slX[tid * 11 + k] = cix[k];
    }

    // per-warp extraction: 10 rounds, f32 butterflies
    {
        int cp = 0, ip = 0;
        #pragma unroll 1
        for (int k = 0; k < CAND; k++) {
            // iou (max, values only; consume lowest tied lane)
            float viou = slI[tid * 11 + ip];
            float mi = viou;
            #pragma unroll
            for (int off = 16; off > 0; off >>= 1)
                mi = fmaxf(mi, __shfl_xor_sync(0xffffffffu, mi, off));
            unsigned msk = __ballot_sync(0xffffffffu, viou == mi);
            if (lane == (int)(__ffs(msk) - 1)) ip++;

            // cost (min, exact (value, index) tie-break)
            float vc = slC[tid * 11 + cp];
            int   myi = (int)slX[tid * 11 + cp];
            float mc = vc;
            #pragma unroll
            for (int off = 16; off > 0; off >>= 1)
                mc = fminf(mc, __shfl_xor_sync(0xffffffffu, mc, off));
            int cand = (vc == mc) ? myi : 0x7fffffff;
            #pragma unroll
            for (int off = 16; off > 0; off >>= 1)
                cand = min(cand, __shfl_xor_sync(0xffffffffu, cand, off));
            if (vc == mc && myi == cand) cp++;

            if (lane == 0) {
                smIw[wid * CAND + k] = mi;
                smCw[wid * CAND + k] = mc;
                smCi[wid * CAND + k] = cand;
            }
        }
    }
    __syncthreads();

    // final merge over 8*10 = 80 entries by warp0 (3 regs/lane)
    if (wid == 0) {
        float c0 = smCw[lane];
        float c1 = smCw[32 + lane];
        float c2 = (lane < NW * CAND - 64) ? smCw[64 + lane] : CSENT;
        int   x0 = smCi[lane];
        int   x1 = smCi[32 + lane];
        int   x2 = (lane < NW * CAND - 64) ? smCi[64 + lane] : 0x7fffffff;
        float i0 = smIw[lane];
        float i1 = smIw[32 + lane];
        float i2 = (lane < NW * CAND - 64) ? smIw[64 + lane] : ISENT;

        float isum = 0.f;
        int   cwin[CAND];
        #pragma unroll
        for (int k = 0; k < CAND; k++) {
            // iou max round
            float mi = fmaxf(fmaxf(i0, i1), i2);
            #pragma unroll
            for (int off = 16; off > 0; off >>= 1)
                mi = fmaxf(mi, __shfl_xor_sync(0xffffffffu, mi, off));
            isum += mi;
            unsigned m0 = __ballot_sync(0xffffffffu, i0 == mi);
            if (m0) { if (lane == (int)(__ffs(m0) - 1)) i0 = ISENT; }
            else {
                unsigned m1 = __ballot_sync(0xffffffffu, i1 == mi);
                if (m1) { if (lane == (int)(__ffs(m1) - 1)) i1 = ISENT; }
                else {
                    unsigned m2 = __ballot_sync(0xffffffffu, i2 == mi);
                    if (lane == (int)(__ffs(m2) - 1)) i2 = ISENT;
                }
            }

            // cost min round with exact index tie-break
            float mc = fminf(fminf(c0, c1), c2);
            #pragma unroll
            for (int off = 16; off > 0; off >>= 1)
                mc = fminf(mc, __shfl_xor_sync(0xffffffffu, mc, off));
            int cand = min(min((c0 == mc) ? x0 : 0x7fffffff,
                               (c1 == mc) ? x1 : 0x7fffffff),
                               (c2 == mc) ? x2 : 0x7fffffff);
            #pragma unroll
            for (int off = 16; off > 0; off >>= 1)
                cand = min(cand, __shfl_xor_sync(0xffffffffu, cand, off));
            if (c0 == mc && x0 == cand) c0 = CSENT;
            else if (c1 == mc && x1 == cand) c1 = CSENT;
            else if (c2 == mc && x2 == cand) c2 = CSENT;
            cwin[k] = cand;
        }

        if (lane == 0) {
            int dynk = (int)isum;          // trunc, matches astype(int32)
            if (dynk < 1) dynk = 1;
            int g = bg & 15;
            #pragma unroll
            for (int k = 0; k < CAND; k++) {
                if (k < dynk) {
                    int idx = b * NA + cwin[k];
                    int old = atomicAdd(&g_cnt[idx], 1);
                    atomicAdd(&g_gsum[idx], g);
                    if (old == 0) {
                        int pos = atomicAdd(&g_nfg, 1);
                        g_list[pos] = idx;
                    }
                }
            }
        }
    }
}

// ---------------- fg-only losses + fused final combine + state reset ---------
__global__ void kLoss(const float* __restrict__ p8, const float* __restrict__ p16,
                      const float* __restrict__ p32, const float* __restrict__ gtb,
                      const int* __restrict__ gtc, float* out) {
    int gid  = blockIdx.x * blockDim.x + threadIdx.x;
    int wi   = gid >> 5;
    int lane = gid & 31;

    float lb = 0.f, lcf = 0.f, lcl = 0.f, nf = 0.f;
    if (wi < g_nfg) {
        int idx = g_list[wi];
        int b = idx / NA, a = idx - b * NA;
        int cnt = g_cnt[idx];
        int gi = (cnt == 1) ? g_gsum[idx] : g_best[idx];
        int ii = g_ia[idx];
        float miou = g_ci[((size_t)(b * NG + gi)) * NA + ii].y;
        int tc = gtc[b * NG + gi];
        const float* P; int HW, loc, w; float s;
        level_of(a, b, p8, p16, p32, &P, &HW, &loc, &s, &w);
        P += loc;

        // 80 classes across 32 lanes; fast BCE (verified identical rel_err R13)
        {
            int c0 = lane, c1 = lane + 32;
            float x0 = P[(5 + c0) * HW];
            float x1 = P[(5 + c1) * HW];
            float t0 = (c0 == tc) ? miou : 0.f;
            float t1 = (c1 == tc) ? miou : 0.f;
            lcl  = fmaxf(x0, 0.f) - x0 * t0 + __logf(1.f + __expf(-fabsf(x0)));
            lcl += fmaxf(x1, 0.f) - x1 * t1 + __logf(1.f + __expf(-fabsf(x1)));
            if (lane < 16) {
                int c2 = lane + 64;
                float x2 = P[(5 + c2) * HW];
                float t2 = (c2 == tc) ? miou : 0.f;
                lcl += fmaxf(x2, 0.f) - x2 * t2 + __logf(1.f + __expf(-fabsf(x2)));
            }
        }

        if (lane == 0) {
            float bx = g_pbox[idx * 4 + 0], by = g_pbox[idx * 4 + 1];
            float bw = g_pbox[idx * 4 + 2], bh = g_pbox[idx * 4 + 3];
            const float* gb = gtb + (b * NG + gi) * 4;
            float cx = gb[0], cy = gb[1], gw = gb[2], gh = gb[3];
            float tlx = fmaxf(bx - bw * 0.5f, cx - gw * 0.5f);
            float tly = fmaxf(by - bh * 0.5f, cy - gh * 0.5f);
            float brx = fminf(bx + bw * 0.5f, cx + gw * 0.5f);
            float bry = fminf(by + bh * 0.5f, cy + gh * 0.5f);
            float iw = fmaxf(brx - tlx, 0.f), ih = fmaxf(bry - tly, 0.f);
            float inter = iw * ih;
            float ioue = inter / (bw * bh + gw * gh - inter + 1e-16f);
            lb = 1.f - ioue * ioue;
            nf = 1.f;
            lcf = -P[4 * HW];   // -x*fg term; softplus summed in kA1
        }
    }
    reduce4(lb, lcf, lcl, nf);

    // last-block-done: final combine + reset state for next invocation
    if (threadIdx.x == 0) {
        __threadfence();
        int t = atomicAdd(&g_done, 1);
        if (t == (int)gridDim.x - 1) {
            double nfg = g_acc[3];
            if (nfg < 1.0) nfg = 1.0;
            out[0] = (float)((5.0 * g_acc[0] + g_acc[1] + g_acc[2]) / nfg);
            // reset for next kernel_launch (globals are zero-init at load)
            g_acc[0] = 0.0; g_acc[1] = 0.0; g_acc[2] = 0.0; g_acc[3] = 0.0;
            g_nfg = 0;
            g_done = 0;
            #pragma unroll
            for (int i = 0; i < NB; i++) g_ucnt[i] = 0;
        }
    }
}

// ---------------- launcher -----------------------------------------------------
extern "C" void kernel_launch(void* const* d_in, const int* in_sizes, int n_in,
                              void* d_out, int out_size) {
    const float* p8  = (const float*)d_in[0];
    const float* p16 = (const float*)d_in[1];
    const float* p32 = (const float*)d_in[2];
    const float* gtb = (const float*)d_in[3];
    const int*   gtc = (const int*)d_in[4];
    (void)in_sizes; (void)n_in; (void)out_size;

    dim3 grid((NA + 255) / 256, NB);
    kA1<<<grid, 256>>>(p8, p16, p32, gtb);
    kA2<<<grid, 256>>>(p8, p16, p32, gtb, gtc);
    kB<<<NB * NG, 256>>>();
    kLoss<<<LOSS_BLOCKS, 256>>>(p8, p16, p32, gtb, gtc, (float*)d_out);
}

// round 16
// speedup vs baseline: 1.6825x; 1.0357x over previous
#include <cuda_runtime.h>
#include <math.h>
#include <stdint.h>

#define NB 32
#define NG 16
#define NA 8400
#define NCLS 80
#define CAND 10
#define MAXFG (NB * NG * CAND)
#define LOSS_BLOCKS ((MAXFG * 32 + 255) / 256)

// ---------------- scratch (device globals; zero-initialized at load,
// re-zeroed by kLoss's last block for the next invocation) -------------------
__device__ float2        g_ci  [(size_t)NB * NG * NA];   // (cost, iou), COMPACT i indexed
__device__ float         g_pbox[(size_t)NB * NA * 4];
__device__ int           g_ia  [(size_t)NB * NA];        // anchor -> compact index
__device__ int           g_best[(size_t)NB * NA];
__device__ int           g_cnt [(size_t)NB * NA];
__device__ int           g_gsum[(size_t)NB * NA];
__device__ int           g_ulist[(size_t)NB * NA];       // per-b packed: a | (interM<<16)
__device__ int           g_ucnt[NB];
__device__ int           g_list[MAXFG];
__device__ int           g_nfg;
__device__ int           g_done;
__device__ double        g_acc[4];   // loss_box, loss_conf, loss_cls, n_fg

static __device__ __forceinline__ void level_of(int a, int b,
                                                const float* p8, const float* p16, const float* p32,
                                                const float** P, int* HW, int* loc, float* s, int* w) {
    if (a < 6400)      { *P = p8  + (size_t)b * 85 * 6400; *HW = 6400; *loc = a;        *s = 8.f;  *w = 80; }
    else if (a < 8000) { *P = p16 + (size_t)b * 85 * 1600; *HW = 1600; *loc = a - 6400; *s = 16.f; *w = 40; }
    else               { *P = p32 + (size_t)b * 85 * 400;  *HW = 400;  *loc = a - 8000; *s = 32.f; *w = 20; }
}

static __device__ __forceinline__ void reduce1(float v, int slot) {
    int tid = threadIdx.x, lane = tid & 31, wid = tid >> 5;
    #pragma unroll
    for (int off = 16; off > 0; off >>= 1) v += __shfl_down_sync(0xffffffffu, v, off);
    __shared__ float sw[8];
    if (lane == 0) sw[wid] = v;
    __syncthreads();
    if (tid == 0) {
        float a0 = 0.f;
        #pragma unroll
        for (int i = 0; i < 8; i++) a0 += sw[i];
        atomicAdd(&g_acc[slot], (double)a0);
    }
}

static __device__ __forceinline__ void reduce4(float v0, float v1, float v2, float v3) {
    int tid = threadIdx.x, lane = tid & 31, wid = tid >> 5;
    #pragma unroll
    for (int off = 16; off > 0; off >>= 1) {
        v0 += __shfl_down_sync(0xffffffffu, v0, off);
        v1 += __shfl_down_sync(0xffffffffu, v1, off);
        v2 += __shfl_down_sync(0xffffffffu, v2, off);
        v3 += __shfl_down_sync(0xffffffffu, v3, off);
    }
    __shared__ float sw[8][4];
    if (lane == 0) { sw[wid][0] = v0; sw[wid][1] = v1; sw[wid][2] = v2; sw[wid][3] = v3; }
    __syncthreads();
    if (tid == 0) {
        float a0 = 0, a1 = 0, a2 = 0, a3 = 0;
        #pragma unroll
        for (int i = 0; i < 8; i++) { a0 += sw[i][0]; a1 += sw[i][1]; a2 += sw[i][2]; a3 += sw[i][3]; }
        if (a0 != 0.f) atomicAdd(&g_acc[0], (double)a0);
        if (a1 != 0.f) atomicAdd(&g_acc[1], (double)a1);
        if (a2 != 0.f) atomicAdd(&g_acc[2], (double)a2);
        if (a3 != 0.f) atomicAdd(&g_acc[3], (double)a3);
    }
}

// ---------------- kernel A1: geometry only (all anchors) ---------------------
__global__ void kA1(const float* __restrict__ p8, const float* __restrict__ p16,
                    const float* __restrict__ p32, const float* __restrict__ gtb) {
    int b   = blockIdx.y;
    int tid = threadIdx.x;
    int a   = blockIdx.x * blockDim.x + tid;

    __shared__ float sB[NG * 4];
    if (tid < NG * 4) sB[tid] = gtb[b * NG * 4 + tid];
    __syncthreads();

    float softp = 0.f;
    bool  uni = false;
    unsigned interM = 0;

    if (a < NA) {
        const float* P; int HW, loc, w; float s;
        level_of(a, b, p8, p16, p32, &P, &HW, &loc, &s, &w);
        P += loc;
        int ix = loc % w, iy = loc / w;
        float xc = ((float)ix + 0.5f) * s;
        float yc = ((float)iy + 0.5f) * s;
        float r2 = 2.5f * s;

        float cf = P[4 * HW];
        // fast softplus: output-side sum; verified identical rel_err in R13
        softp = fmaxf(cf, 0.f) + __logf(1.f + __expf(-fabsf(cf)));

        int idx = b * NA + a;
        g_cnt[idx] = 0;
        g_gsum[idx] = 0;

        #pragma unroll
        for (int g = 0; g < NG; g++) {
            float cx = sB[g * 4 + 0], cy = sB[g * 4 + 1];
            float gw = sB[g * 4 + 2], gh = sB[g * 4 + 3];
            float gminx = cx - gw * 0.5f, gmaxx = cx + gw * 0.5f;
            float gminy = cy - gh * 0.5f, gmaxy = cy + gh * 0.5f;
            bool inb = (xc - gminx > 0.f) && (gmaxx - xc > 0.f) &&
                       (yc - gminy > 0.f) && (gmaxy - yc > 0.f);
            bool inm = (xc - (cx - r2) > 0.f) && ((cx + r2) - xc > 0.f) &&
                       (yc - (cy - r2) > 0.f) && ((cy + r2) - yc > 0.f);
            if (inb && inm) interM |= (1u << g);
            uni = uni || inb || inm;
        }
    }

    // warp-aggregated append to per-image union list
    unsigned mask = __ballot_sync(0xffffffffu, uni);
    if (uni) {
        int leader = __ffs(mask) - 1;
        int rank   = __popc(mask & ((1u << (tid & 31)) - 1u));
        int base = 0;
        if ((tid & 31) == leader) base = atomicAdd(&g_ucnt[b], __popc(mask));
        base = __shfl_sync(mask, base, leader);
        g_ulist[b * NA + base + rank] = a | ((int)interM << 16);
    }

    reduce1(softp, 1);
}

// ---------------- kernel A2: heavy math over compacted union list ------------
__global__ void kA2(const float* __restrict__ p8, const float* __restrict__ p16,
                    const float* __restrict__ p32, const float* __restrict__ gtb,
                    const int* __restrict__ gtc) {
    int b   = blockIdx.y;
    int tid = threadIdx.x;
    int i   = blockIdx.x * blockDim.x + tid;

    // early exit BEFORE smem setup: ~95% of blocks have no work
    int n = g_ucnt[b];
    if (blockIdx.x * blockDim.x >= n) return;

    __shared__ float sB[NG * 4];
    __shared__ int   sC[NG];
    __shared__ int   sSlot[NCLS];          // class -> g-slot (-1 none)
    __shared__ float sD[NG * 256];         // per-thread d for each used slot

    if (tid < NG * 4) sB[tid] = gtb[b * NG * 4 + tid];
    if (tid < NG)     sC[tid] = gtc[b * NG + tid];
    if (tid < NCLS)   sSlot[tid] = -1;
    __syncthreads();
    if (tid == 0) {
        #pragma unroll
        for (int g = 0; g < NG; g++)
            if (sSlot[sC[g]] < 0) sSlot[sC[g]] = g;
    }
    __syncthreads();

    if (i >= n) return;

    int packed = g_ulist[b * NA + i];
    int a      = packed & 0xffff;
    unsigned interM = (unsigned)packed >> 16;

    const float* P; int HW, loc, w; float s;
    level_of(a, b, p8, p16, p32, &P, &HW, &loc, &s, &w);
    P += loc;
    int ix = loc % w, iy = loc / w;
    int idx = b * NA + a;
    g_ia[idx] = i;

    // decode (precise: feeds iou -> dyn_k and box loss)
    float px = P[0], py = P[HW], pw = P[2 * HW], ph = P[3 * HW];
    float cf = P[4 * HW];
    float bx = (px + (float)ix) * s;
    float by = (py + (float)iy) * s;
    float bw = expf(pw) * s;
    float bh = expf(ph) * s;
    g_pbox[idx * 4 + 0] = bx; g_pbox[idx * 4 + 1] = by;
    g_pbox[idx * 4 + 2] = bw; g_pbox[idx * 4 + 3] = bh;

    float rr = rsqrtf(1.f + __expf(-cf));   // sqrt(sigmoid(cf))

    // suml1 = sum_c log(1-p_c) with oct-grouped logs; stash d = log(p)-log(1-p)
    float s2 = 0.f;
    #pragma unroll 2
    for (int c8 = 0; c8 < NCLS; c8 += 8) {
        float prod = 1.f;
        #pragma unroll
        for (int j = 0; j < 8; j++) {
            int c = c8 + j;
            float x = P[(5 + c) * HW];
            float p = rr * rsqrtf(1.f + __expf(-x));
            float t = fmaxf(1.f - p, 1e-12f);
            prod *= t;
            int slot = sSlot[c];
            if (slot >= 0)
                sD[slot * 256 + tid] = __logf(fmaxf(p, 1e-12f)) - __logf(t);
        }
        s2 += __log2f(prod);
    }
    float suml1 = s2 * 0.69314718055994531f;

    float areab = bw * bh;
    float bhw = bw * 0.5f, bhh = bh * 0.5f;
    float bestc = 3.402823466e38f;
    int   bestg = 0;
    size_t base = ((size_t)b * NG) * NA + i;   // compact-i indexed planes

    for (int g = 0; g < NG; g++) {
        float cx = sB[g * 4 + 0], cy = sB[g * 4 + 1];
        float gw = sB[g * 4 + 2], gh = sB[g * 4 + 3];
        int   slot = sSlot[sC[g]];
        float d  = sD[slot * 256 + tid];
        float cls_cost = -(d + suml1);

        float tlx = fmaxf(cx - gw * 0.5f, bx - bhw);
        float tly = fmaxf(cy - gh * 0.5f, by - bhh);
        float brx = fminf(cx + gw * 0.5f, bx + bhw);
        float bry = fminf(cy + gh * 0.5f, by + bhh);
        float iw = fmaxf(brx - tlx, 0.f), ih = fmaxf(bry - tly, 0.f);
        float inter = iw * ih;
        float iou = inter / (gw * gh + areab - inter + 1e-16f);

        float cost = cls_cost - 3.f * __logf(iou + 1e-8f) +
                     (((interM >> g) & 1u) ? 0.f : 100000.f);
        if (cost < bestc) { bestc = cost; bestg = g; }

        g_ci[base + (size_t)g * NA] = make_float2(cost, iou);
    }
    g_best[idx] = bestg;
}

// ---------------- kernel B: T=256, f32 extraction, exact tie-break -----------
__global__ void kB() {
    const int T = 256;
    const int NW = 8;
    const float CSENT = 3.402823466e38f;
    const float ISENT = -1e30f;
    int bg  = blockIdx.x;          // b*16 + g
    int b   = bg >> 4;
    int tid = threadIdx.x;
    int lane = tid & 31, wid = tid >> 5;
    size_t cbase = (size_t)bg * NA;   // compact-i indexed

    float cv[CAND], iv[CAND];
    unsigned short cix[CAND];
    #pragma unroll
    for (int k = 0; k < CAND; k++) { cv[k] = CSENT; iv[k] = ISENT; cix[k] = 0; }

    int n = g_ucnt[b];
    for (int i = tid; i < n; i += T) {
        int a = g_ulist[b * NA + i] & 0xffff;
        float2 ci = g_ci[cbase + i];   // coalesced
        // min-cost list: strict < keeps encounter order (= index asc) for ties
        if (ci.x < cv[CAND - 1]) {
            float v = ci.x; unsigned short id = (unsigned short)a;
            #pragma unroll
            for (int k = 0; k < CAND; k++)
                if (v < cv[k]) {
                    float tv = cv[k]; cv[k] = v; v = tv;
                    unsigned short ti = cix[k]; cix[k] = id; id = ti;
                }
        }
        // max-iou list (values only)
        if (ci.y > iv[CAND - 1]) {
            float v = ci.y;
            #pragma unroll
            for (int k = 0; k < CAND; k++)
                if (v > iv[k]) { float tv = iv[k]; iv[k] = v; v = tv; }
        }
    }

    // dump lists to smem (stride 11 -> conflict-free)
    __shared__ float          slC[T * 11], slI[T * 11];
    __shared__ unsigned short slX[T * 11];
    __shared__ float          smCw[NW * CAND], smIw[NW * CAND];
    __shared__ int            smCi[NW * CAND];
    #pragma unroll
    for (int k = 0; k < CAND; k++) {
        slC[tid * 11 + k] = cv[k];
        slI[tid * 11 + k] = iv[k];
        slX[tid * 11 + k] = cix[k];
    }

    // per-warp extraction: 10 rounds, f32 butterflies
    {
        int cp = 0, ip = 0;
        #pragma unroll 1
        for (int k = 0; k < CAND; k++) {
            // iou (max, values only; consume lowest tied lane)
            float viou = slI[tid * 11 + ip];
            float mi = viou;
            #pragma unroll
            for (int off = 16; off > 0; off >>= 1)
                mi = fmaxf(mi, __shfl_xor_sync(0xffffffffu, mi, off));
            unsigned msk = __ballot_sync(0xffffffffu, viou == mi);
            if (lane == (int)(__ffs(msk) - 1)) ip++;

            // cost (min, exact (value, index) tie-break)
            float vc = slC[tid * 11 + cp];
            int   myi = (int)slX[tid * 11 + cp];
            float mc = vc;
            #pragma unroll
            for (int off = 16; off > 0; off >>= 1)
                mc = fminf(mc, __shfl_xor_sync(0xffffffffu, mc, off));
            int cand = (vc == mc) ? myi : 0x7fffffff;
            #pragma unroll
            for (int off = 16; off > 0; off >>= 1)
                cand = min(cand, __shfl_xor_sync(0xffffffffu, cand, off));
            if (vc == mc && myi == cand) cp++;

            if (lane == 0) {
                smIw[wid * CAND + k] = mi;
                smCw[wid * CAND + k] = mc;
                smCi[wid * CAND + k] = cand;
            }
        }
    }
    __syncthreads();

    // final merge over 8*10 = 80 entries by warp0 (3 regs/lane)
    if (wid == 0) {
        float c0 = smCw[lane];
        float c1 = smCw[32 + lane];
        float c2 = (lane < NW * CAND - 64) ? smCw[64 + lane] : CSENT;
        int   x0 = smCi[lane];
        int   x1 = smCi[32 + lane];
        int   x2 = (lane < NW * CAND - 64) ? smCi[64 + lane] : 0x7fffffff;
        float i0 = smIw[lane];
        float i1 = smIw[32 + lane];
        float i2 = (lane < NW * CAND - 64) ? smIw[64 + lane] : ISENT;

        float isum = 0.f;
        int   cwin[CAND];
        #pragma unroll
        for (int k = 0; k < CAND; k++) {
            // iou max round
            float mi = fmaxf(fmaxf(i0, i1), i2);
            #pragma unroll
            for (int off = 16; off > 0; off >>= 1)
                mi = fmaxf(mi, __shfl_xor_sync(0xffffffffu, mi, off));
            isum += mi;
            unsigned m0 = __ballot_sync(0xffffffffu, i0 == mi);
            if (m0) { if (lane == (int)(__ffs(m0) - 1)) i0 = ISENT; }
            else {
                unsigned m1 = __ballot_sync(0xffffffffu, i1 == mi);
                if (m1) { if (lane == (int)(__ffs(m1) - 1)) i1 = ISENT; }
                else {
                    unsigned m2 = __ballot_sync(0xffffffffu, i2 == mi);
                    if (lane == (int)(__ffs(m2) - 1)) i2 = ISENT;
                }
            }

            // cost min round with exact index tie-break
            float mc = fminf(fminf(c0, c1), c2);
            #pragma unroll
            for (int off = 16; off > 0; off >>= 1)
                mc = fminf(mc, __shfl_xor_sync(0xffffffffu, mc, off));
            int cand = min(min((c0 == mc) ? x0 : 0x7fffffff,
                               (c1 == mc) ? x1 : 0x7fffffff),
                               (c2 == mc) ? x2 : 0x7fffffff);
            #pragma unroll
            for (int off = 16; off > 0; off >>= 1)
                cand = min(cand, __shfl_xor_sync(0xffffffffu, cand, off));
            if (c0 == mc && x0 == cand) c0 = CSENT;
            else if (c1 == mc && x1 == cand) c1 = CSENT;
            else if (c2 == mc && x2 == cand) c2 = CSENT;
            cwin[k] = cand;
        }

        if (lane == 0) {
            int dynk = (int)isum;          // trunc, matches astype(int32)
            if (dynk < 1) dynk = 1;
            int g = bg & 15;
            #pragma unroll
            for (int k = 0; k < CAND; k++) {
                if (k < dynk) {
                    int idx = b * NA + cwin[k];
                    int old = atomicAdd(&g_cnt[idx], 1);
                    atomicAdd(&g_gsum[idx], g);
                    if (old == 0) {
                        int pos = atomicAdd(&g_nfg, 1);
                        g_list[pos] = idx;
                    }
                }
            }
        }
    }
}

// ---------------- fg-only losses + fused final combine + state reset ---------
__global__ void kLoss(const float* __restrict__ p8, const float* __restrict__ p16,
                      const float* __restrict__ p32, const float* __restrict__ gtb,
                      const int* __restrict__ gtc, float* out) {
    int gid  = blockIdx.x * blockDim.x + threadIdx.x;
    int wi   = gid >> 5;
    int lane = gid & 31;

    float lb = 0.f, lcf = 0.f, lcl = 0.f, nf = 0.f;
    if (wi < g_nfg) {
        int idx = g_list[wi];
        int b = idx / NA, a = idx - b * NA;
        int cnt = g_cnt[idx];
        int gi = (cnt == 1) ? g_gsum[idx] : g_best[idx];
        int ii = g_ia[idx];
        float miou = g_ci[((size_t)(b * NG + gi)) * NA + ii].y;
        int tc = gtc[b * NG + gi];
        const float* P; int HW, loc, w; float s;
        level_of(a, b, p8, p16, p32, &P, &HW, &loc, &s, &w);
        P += loc;

        // 80 classes across 32 lanes; fast BCE (verified identical rel_err R13)
        {
            int c0 = lane, c1 = lane + 32;
            float x0 = P[(5 + c0) * HW];
            float x1 = P[(5 + c1) * HW];
            float t0 = (c0 == tc) ? miou : 0.f;
            float t1 = (c1 == tc) ? miou : 0.f;
            lcl  = fmaxf(x0, 0.f) - x0 * t0 + __logf(1.f + __expf(-fabsf(x0)));
            lcl += fmaxf(x1, 0.f) - x1 * t1 + __logf(1.f + __expf(-fabsf(x1)));
            if (lane < 16) {
                int c2 = lane + 64;
                float x2 = P[(5 + c2) * HW];
                float t2 = (c2 == tc) ? miou : 0.f;
                lcl += fmaxf(x2, 0.f) - x2 * t2 + __logf(1.f + __expf(-fabsf(x2)));
            }
        }

        if (lane == 0) {
            float bx = g_pbox[idx * 4 + 0], by = g_pbox[idx * 4 + 1];
            float bw = g_pbox[idx * 4 + 2], bh = g_pbox[idx * 4 + 3];
            const float* gb = gtb + (b * NG + gi) * 4;
            float cx = gb[0], cy = gb[1], gw = gb[2], gh = gb[3];
            float tlx = fmaxf(bx - bw * 0.5f, cx - gw * 0.5f);
            float tly = fmaxf(by - bh * 0.5f, cy - gh * 0.5f);
            float brx = fminf(bx + bw * 0.5f, cx + gw * 0.5f);
            float bry = fminf(by + bh * 0.5f, cy + gh * 0.5f);
            float iw = fmaxf(brx - tlx, 0.f), ih = fmaxf(bry - tly, 0.f);
            float inter = iw * ih;
            float ioue = inter / (bw * bh + gw * gh - inter + 1e-16f);
            lb = 1.f - ioue * ioue;
            nf = 1.f;
            lcf = -P[4 * HW];   // -x*fg term; softplus summed in kA1
        }
    }
    reduce4(lb, lcf, lcl, nf);

    // last-block-done: final combine + reset state for next invocation
    if (threadIdx.x == 0) {
        __threadfence();
        int t = atomicAdd(&g_done, 1);
        if (t == (int)gridDim.x - 1) {
            double nfg = g_acc[3];
            if (nfg < 1.0) nfg = 1.0;
            out[0] = (float)((5.0 * g_acc[0] + g_acc[1] + g_acc[2]) / nfg);
            // reset for next kernel_launch (globals are zero-init at load)
            g_acc[0] = 0.0; g_acc[1] = 0.0; g_acc[2] = 0.0; g_acc[3] = 0.0;
            g_nfg = 0;
            g_done = 0;
            #pragma unroll
            for (int i = 0; i < NB; i++) g_ucnt[i] = 0;
        }
    }
}

// ---------------- launcher -----------------------------------------------------
extern "C" void kernel_launch(void* const* d_in, const int* in_sizes, int n_in,
                              void* d_out, int out_size) {
    const float* p8  = (const float*)d_in[0];
    const float* p16 = (const float*)d_in[1];
    const float* p32 = (const float*)d_in[2];
    const float* gtb = (const float*)d_in[3];
    const int*   gtc = (const int*)d_in[4];
    (void)in_sizes; (void)n_in; (void)out_size;

    dim3 grid((NA + 255) / 256, NB);
    kA1<<<grid, 256>>>(p8, p16, p32, gtb);
    kA2<<<grid, 256>>>(p8, p16, p32, gtb, gtc);
    kB<<<NB * NG, 256>>>();
    kLoss<<<LOSS_BLOCKS, 256>>>(p8, p16, p32, gtb, gtc, (float*)d_out);
}